// round 1
// baseline (speedup 1.0000x reference)
#include <cuda_runtime.h>
#include <math.h>

// Problem constants
#define Bc   64
#define Sc   512
#define Dc   512
#define Hc   8
#define DKc  64
#define Lc   4
#define DFFc 2048
#define NSKc 300
#define FC1c 512
#define FC2c 256
#define Mr   (Bc * Sc)   // 32768 rows

// ---------------- scratch (device globals; no allocations allowed) ----------
__device__ float g_qe[(size_t)Mr * Dc];
__device__ float g_x [(size_t)Mr * Dc];
__device__ float g_y [(size_t)Mr * Dc];
__device__ float g_K [(size_t)Mr * Dc];
__device__ float g_V [(size_t)Mr * Dc];
__device__ float g_O [(size_t)Mr * Dc];
__device__ float g_P [(size_t)Mr * Dc];
__device__ float g_F1[(size_t)Mr * DFFc];
__device__ float g_C [(size_t)Mr * 2 * Dc];
__device__ float g_H1[(size_t)Mr * FC1c];
__device__ float g_H2[(size_t)Mr * FC2c];

// ---------------- embed: qe, x = qe+pe, y = qa_emb[target]+qe+pe ------------
__global__ void embed_kernel(const int* __restrict__ q_data,
                             const int* __restrict__ target,
                             const float* __restrict__ pe,
                             const float* __restrict__ q_emb,
                             const float* __restrict__ qa_emb) {
    size_t idx = (size_t)blockIdx.x * blockDim.x + threadIdx.x;
    if (idx >= (size_t)Mr * Dc) return;
    int bs = (int)(idx / Dc);
    int d  = (int)(idx % Dc);
    int s  = bs % Sc;
    float qe = q_emb[(size_t)q_data[bs] * Dc + d];
    float p  = pe[(size_t)s * Dc + d];
    g_qe[idx] = qe;
    g_x [idx] = qe + p;
    g_y [idx] = qa_emb[(size_t)target[bs] * Dc + d] + qe + p;
}

// ---------------- tiled fp32 GEMM: C = [relu](A @ W + bias) -----------------
// A [M,K] row-major, W [K,N] row-major, C [M,N]. M % 128 == 0, K % 8 == 0.
#define BM 128
#define BN 128
#define BK 8

__global__ __launch_bounds__(256)
void gemm_bias_kernel(const float* __restrict__ A, const float* __restrict__ W,
                      const float* __restrict__ bias, float* __restrict__ C,
                      int M, int K, int N, int relu) {
    __shared__ float As[BK][BM + 4];
    __shared__ float Bs[BK][BN];
    const int tid = threadIdx.x;            // 256 threads
    const int m0 = blockIdx.y * BM;
    const int n0 = blockIdx.x * BN;
    const int tx = tid & 15;                // 0..15 (N dim)
    const int ty = tid >> 4;                // 0..15 (M dim)

    const int ar = tid >> 1;                // A tile row 0..127
    const int ac = (tid & 1) * 4;           // A tile col 0 or 4
    const int bk = tid >> 5;                // B tile row 0..7
    const int bn = (tid & 31) * 4;          // B tile col 0..124
    const bool nfull = (n0 + BN <= N);

    float acc[8][8];
    #pragma unroll
    for (int i = 0; i < 8; i++)
        #pragma unroll
        for (int j = 0; j < 8; j++) acc[i][j] = 0.f;

    for (int k0 = 0; k0 < K; k0 += BK) {
        float4 av = *(const float4*)(A + (size_t)(m0 + ar) * K + k0 + ac);
        As[ac + 0][ar] = av.x;
        As[ac + 1][ar] = av.y;
        As[ac + 2][ar] = av.z;
        As[ac + 3][ar] = av.w;
        if (nfull) {
            *(float4*)&Bs[bk][bn] =
                *(const float4*)(W + (size_t)(k0 + bk) * N + n0 + bn);
        } else {
            #pragma unroll
            for (int j = 0; j < 4; j++) {
                int n = n0 + bn + j;
                Bs[bk][bn + j] = (n < N) ? W[(size_t)(k0 + bk) * N + n] : 0.f;
            }
        }
        __syncthreads();
        #pragma unroll
        for (int kk = 0; kk < BK; kk++) {
            float a[8], b[8];
            #pragma unroll
            for (int i = 0; i < 8; i++) a[i] = As[kk][ty * 8 + i];
            #pragma unroll
            for (int j = 0; j < 8; j++) b[j] = Bs[kk][tx * 8 + j];
            #pragma unroll
            for (int i = 0; i < 8; i++)
                #pragma unroll
                for (int j = 0; j < 8; j++) acc[i][j] += a[i] * b[j];
        }
        __syncthreads();
    }

    #pragma unroll
    for (int i = 0; i < 8; i++) {
        int m = m0 + ty * 8 + i;
        #pragma unroll
        for (int j = 0; j < 8; j++) {
            int n = n0 + tx * 8 + j;
            if (n < N) {
                float v = acc[i][j] + bias[n];
                if (relu) v = fmaxf(v, 0.f);
                C[(size_t)m * N + n] = v;
            }
        }
    }
}

// ---------------- flash attention (Q==K from g_K, V from g_V) ---------------
// strict causal mask (j < i); row i==0 outputs zero (post-softmax row_keep).
// grid: (qtile=8, h=8, b=64), block 256. 4 threads per query row, 16 dims each.
__global__ __launch_bounds__(256)
void attn_kernel() {
    const int qt = blockIdx.x, h = blockIdx.y, b = blockIdx.z;
    const int tid = threadIdx.x;
    const int r = tid >> 2;       // query row within tile 0..63
    const int p = tid & 3;        // dim quarter
    const int i = qt * 64 + r;    // global query position
    const float scale = 0.125f;   // 1/sqrt(64)

    __shared__ float Kt[64][64];
    __shared__ float Vt[64][64];

    float q[16];
    {
        const float* qp = g_K + ((size_t)(b * Sc + i)) * Dc + h * DKc + p * 16;
        #pragma unroll
        for (int w = 0; w < 4; w++) {
            float4 v = *(const float4*)(qp + w * 4);
            q[w * 4 + 0] = v.x; q[w * 4 + 1] = v.y;
            q[w * 4 + 2] = v.z; q[w * 4 + 3] = v.w;
        }
    }

    float m_run = -1e30f, l_run = 0.f;
    float o[16];
    #pragma unroll
    for (int d = 0; d < 16; d++) o[d] = 0.f;

    for (int jt = 0; jt <= qt; jt++) {
        const size_t base = ((size_t)(b * Sc + jt * 64 + r)) * Dc + h * DKc + p * 16;
        #pragma unroll
        for (int w = 0; w < 4; w++) {
            *(float4*)&Kt[r][p * 16 + w * 4] = *(const float4*)(g_K + base + w * 4);
            *(float4*)&Vt[r][p * 16 + w * 4] = *(const float4*)(g_V + base + w * 4);
        }
        __syncthreads();

        // uniform loop (all lanes converged for the shfl reduce); mask per-row
        for (int j = 0; j < 64; j++) {
            float s = 0.f;
            #pragma unroll
            for (int d = 0; d < 16; d++) s += q[d] * Kt[j][p * 16 + d];
            s += __shfl_xor_sync(0xffffffffu, s, 1);
            s += __shfl_xor_sync(0xffffffffu, s, 2);
            s *= scale;
            if (jt * 64 + j < i) {
                float m_new = fmaxf(m_run, s);
                float corr  = __expf(m_run - m_new);
                float pj    = __expf(s - m_new);
                l_run = l_run * corr + pj;
                #pragma unroll
                for (int d = 0; d < 16; d++)
                    o[d] = o[d] * corr + pj * Vt[j][p * 16 + d];
                m_run = m_new;
            }
        }
        __syncthreads();
    }

    float inv = (l_run > 0.f) ? (1.f / l_run) : 0.f;
    float* op = g_O + ((size_t)(b * Sc + i)) * Dc + h * DKc + p * 16;
    #pragma unroll
    for (int d = 0; d < 16; d++) op[d] = o[d] * inv;
}

// ---------------- fused residual add + LayerNorm (in-place on x) ------------
__global__ __launch_bounds__(256)
void add_ln_kernel(float* __restrict__ x, const float* __restrict__ resid,
                   const float* __restrict__ g, const float* __restrict__ b) {
    const int row = blockIdx.x;
    const int tid = threadIdx.x;    // 256, 2 elems each
    const size_t base = (size_t)row * Dc;
    float v0 = x[base + tid]       + resid[base + tid];
    float v1 = x[base + tid + 256] + resid[base + tid + 256];
    float s  = v0 + v1;
    float ss = v0 * v0 + v1 * v1;

    __shared__ float sbuf[8], ssbuf[8];
    #pragma unroll
    for (int o = 16; o > 0; o >>= 1) {
        s  += __shfl_xor_sync(0xffffffffu, s, o);
        ss += __shfl_xor_sync(0xffffffffu, ss, o);
    }
    if ((tid & 31) == 0) { sbuf[tid >> 5] = s; ssbuf[tid >> 5] = ss; }
    __syncthreads();
    if (tid < 32) {
        s  = (tid < 8) ? sbuf[tid]  : 0.f;
        ss = (tid < 8) ? ssbuf[tid] : 0.f;
        #pragma unroll
        for (int o = 4; o > 0; o >>= 1) {
            s  += __shfl_xor_sync(0xffffffffu, s, o);
            ss += __shfl_xor_sync(0xffffffffu, ss, o);
        }
        if (tid == 0) { sbuf[0] = s; ssbuf[0] = ss; }
    }
    __syncthreads();
    float mean = sbuf[0] * (1.f / 512.f);
    float var  = ssbuf[0] * (1.f / 512.f) - mean * mean;
    float rstd = rsqrtf(var + 1e-5f);
    x[base + tid]       = (v0 - mean) * rstd * g[tid]       + b[tid];
    x[base + tid + 256] = (v1 - mean) * rstd * g[tid + 256] + b[tid + 256];
}

// ---------------- concat [x | qe] -------------------------------------------
__global__ void concat_kernel() {
    size_t idx = (size_t)blockIdx.x * blockDim.x + threadIdx.x;
    if (idx >= (size_t)Mr * 2 * Dc) return;
    int bs = (int)(idx / (2 * Dc));
    int c  = (int)(idx % (2 * Dc));
    g_C[idx] = (c < Dc) ? g_x[(size_t)bs * Dc + c]
                        : g_qe[(size_t)bs * Dc + (c - Dc)];
}

// ---------------- launch ----------------------------------------------------
static inline void gemm(const float* A, const float* W, const float* bias,
                        float* C, int M, int K, int N, int relu) {
    dim3 grid((N + BN - 1) / BN, M / BM);
    gemm_bias_kernel<<<grid, 256>>>(A, W, bias, C, M, K, N, relu);
}

extern "C" void kernel_launch(void* const* d_in, const int* in_sizes, int n_in,
                              void* d_out, int out_size) {
    const int*   q_data = (const int*)d_in[0];
    const int*   target = (const int*)d_in[1];
    const float* pe     = (const float*)d_in[2];
    const float* q_emb  = (const float*)d_in[3];
    const float* qa_emb = (const float*)d_in[4];
    const float* Wk     = (const float*)d_in[5];
    const float* bk     = (const float*)d_in[6];
    const float* Wv     = (const float*)d_in[7];
    const float* bv     = (const float*)d_in[8];
    const float* Wo     = (const float*)d_in[9];
    const float* bo     = (const float*)d_in[10];
    const float* ln1_g  = (const float*)d_in[11];
    const float* ln1_b  = (const float*)d_in[12];
    const float* W1     = (const float*)d_in[13];
    const float* b1     = (const float*)d_in[14];
    const float* W2     = (const float*)d_in[15];
    const float* b2     = (const float*)d_in[16];
    const float* ln2_g  = (const float*)d_in[17];
    const float* ln2_b  = (const float*)d_in[18];
    const float* Wout1  = (const float*)d_in[19];
    const float* bout1  = (const float*)d_in[20];
    const float* Wout2  = (const float*)d_in[21];
    const float* bout2  = (const float*)d_in[22];
    const float* Wout3  = (const float*)d_in[23];
    const float* bout3  = (const float*)d_in[24];
    float* out = (float*)d_out;

    float *p_qe, *p_x, *p_y, *p_K, *p_V, *p_O, *p_P, *p_F1, *p_C, *p_H1, *p_H2;
    cudaGetSymbolAddress((void**)&p_qe, g_qe);
    cudaGetSymbolAddress((void**)&p_x,  g_x);
    cudaGetSymbolAddress((void**)&p_y,  g_y);
    cudaGetSymbolAddress((void**)&p_K,  g_K);
    cudaGetSymbolAddress((void**)&p_V,  g_V);
    cudaGetSymbolAddress((void**)&p_O,  g_O);
    cudaGetSymbolAddress((void**)&p_P,  g_P);
    cudaGetSymbolAddress((void**)&p_F1, g_F1);
    cudaGetSymbolAddress((void**)&p_C,  g_C);
    cudaGetSymbolAddress((void**)&p_H1, g_H1);
    cudaGetSymbolAddress((void**)&p_H2, g_H2);

    const int M = Mr;

    // embed
    {
        size_t tot = (size_t)Mr * Dc;
        embed_kernel<<<(unsigned)((tot + 255) / 256), 256>>>(q_data, target, pe, q_emb, qa_emb);
    }

    for (int l = 0; l < Lc; l++) {
        const float* Wk_l = Wk + (size_t)l * Dc * Dc;
        const float* Wv_l = Wv + (size_t)l * Dc * Dc;
        const float* Wo_l = Wo + (size_t)l * Dc * Dc;
        const float* W1_l = W1 + (size_t)l * Dc * DFFc;
        const float* W2_l = W2 + (size_t)l * DFFc * Dc;

        gemm(p_x, Wk_l, bk + l * Dc, p_K, M, Dc, Dc, 0);   // K (== Q)
        gemm(p_y, Wv_l, bv + l * Dc, p_V, M, Dc, Dc, 0);   // V
        attn_kernel<<<dim3(Sc / 64, Hc, Bc), 256>>>();      // flash attention -> g_O
        gemm(p_O, Wo_l, bo + l * Dc, p_P, M, Dc, Dc, 0);   // output proj
        add_ln_kernel<<<M, 256>>>(p_x, p_P, ln1_g + l * Dc, ln1_b + l * Dc);
        gemm(p_x, W1_l, b1 + l * DFFc, p_F1, M, Dc, DFFc, 1);   // FFN up + relu
        gemm(p_F1, W2_l, b2 + l * Dc, p_P, M, DFFc, Dc, 0);     // FFN down
        add_ln_kernel<<<M, 256>>>(p_x, p_P, ln2_g + l * Dc, ln2_b + l * Dc);
    }

    // head
    {
        size_t tot = (size_t)Mr * 2 * Dc;
        concat_kernel<<<(unsigned)((tot + 255) / 256), 256>>>();
    }
    gemm(p_C,  Wout1, bout1, p_H1, M, 2 * Dc, FC1c, 1);
    gemm(p_H1, Wout2, bout2, p_H2, M, FC1c, FC2c, 1);
    gemm(p_H2, Wout3, bout3, out, M, FC2c, NSKc, 0);
}